// round 12
// baseline (speedup 1.0000x reference)
#include <cuda_runtime.h>
#include <cuda_fp16.h>
#include <math.h>
#include <stdint.h>

// ---------------------------------------------------------------------------
// DecoderBlock: B=2, S=2048, D_MODEL=1024, D_COND=512, H=16, d=64, FF=4096
// Round 12: hgemm CTA tile 128x256, warp tile 64x64 (ldm/mma ratio 0.375 ->
// 0.25), 3-stage, 144KB smem, 1 CTA/SM. gb buffer fp16. Attention unchanged.
// ---------------------------------------------------------------------------

#define BS_TOK   4096
#define DM       1024
#define DC       512
#define DFF      4096
#define NH       16
#define DH       64
#define SEQ      2048

// ---------------- scratch ---------------------------------------------------
__device__ __half g_sc  [BS_TOK * DC];
__device__ __half g_gb  [BS_TOK * 4 * DM];   // merged gamma/beta, fp16
__device__ __half g_h   [BS_TOK * DM];
__device__ __half g_qkv [BS_TOK * 3 * DM];
__device__ __half g_attn[BS_TOK * DM];
__device__ float  g_x2  [BS_TOK * DM];
__device__ __half g_ff  [BS_TOK * DFF];
__device__ __half g_wt_p12[4 * DM * DC];
__device__ __half g_wt_qkv[3 * DM * DM];
__device__ __half g_wt_ao [DM * DM];
__device__ __half g_wt_f1 [DFF * DM];
__device__ __half g_wt_f2 [DM * DFF];
__device__ float  g_b_p12 [4 * DM];

// ---------------- helpers ---------------------------------------------------
__device__ __forceinline__ uint32_t smem_u32(const void* p) {
    uint32_t a;
    asm("{ .reg .u64 t; cvta.to.shared.u64 t, %1; cvt.u32.u64 %0, t; }"
        : "=r"(a) : "l"(p));
    return a;
}
__device__ __forceinline__ void cp_async16(uint32_t dst, const void* src) {
    asm volatile("cp.async.cg.shared.global [%0], [%1], 16;"
                 :: "r"(dst), "l"(src) : "memory");
}
#define CP_COMMIT() asm volatile("cp.async.commit_group;" ::: "memory")
#define CP_WAIT(n)  asm volatile("cp.async.wait_group %0;" :: "n"(n) : "memory")

__device__ __forceinline__ void mma_f16(float* c, const uint32_t* a, const uint32_t* b) {
    asm volatile("mma.sync.aligned.m16n8k16.row.col.f32.f16.f16.f32 "
        "{%0,%1,%2,%3}, {%4,%5,%6,%7}, {%8,%9}, {%0,%1,%2,%3};"
        : "+f"(c[0]), "+f"(c[1]), "+f"(c[2]), "+f"(c[3])
        : "r"(a[0]), "r"(a[1]), "r"(a[2]), "r"(a[3]), "r"(b[0]), "r"(b[1]));
}
#define LDMX4(r0, r1, r2, r3, addr)                                           \
    asm volatile("ldmatrix.sync.aligned.m8n8.x4.shared.b16 {%0,%1,%2,%3}, [%4];" \
        : "=r"(r0), "=r"(r1), "=r"(r2), "=r"(r3) : "r"(addr))
#define LDMX4T(r0, r1, r2, r3, addr)                                          \
    asm volatile("ldmatrix.sync.aligned.m8n8.x4.trans.shared.b16 {%0,%1,%2,%3}, [%4];" \
        : "=r"(r0), "=r"(r1), "=r"(r2), "=r"(r3) : "r"(addr))

__device__ __forceinline__ uint32_t packh2(float x, float y) {
    __half2 h = __floats2half2_rn(x, y);
    return *(uint32_t*)&h;
}

#define HXS(r, c) ((uint32_t)((r) * 128 + (((c) ^ ((r) & 7)) << 4)))

// ---------------------------------------------------------------------------
// fp16 mma GEMM: C[M,N] = A[M,K] @ Bt[N,K]^T (+bias)(+gelu)(+res)
// CTA 128x256, warp 64x64 (8 warps, 2x4), BK=64, 3-stage. 144KB smem.
// ---------------------------------------------------------------------------
#define TG_SMEM 147456   // 3*16384 (A) + 3*32768 (B)

template<int BIAS, int GELU, int RES, int OUTH>
__global__ __launch_bounds__(256, 1) void hgemm(
    const __half* __restrict__ A, const __half* __restrict__ Bt,
    const float* __restrict__ bias, const float* __restrict__ res,
    void* __restrict__ Cv, int M, int N, int K)
{
    extern __shared__ __align__(1024) char smem_raw[];
    const uint32_t sA = smem_u32(smem_raw);          // 3 x 16KB
    const uint32_t sB = sA + 3 * 16384;              // 3 x 32KB

    const int tid  = threadIdx.x;
    const int wid  = tid >> 5;
    const int lane = tid & 31;
    const int bx = blockIdx.x, by = blockIdx.y;

    const __half* Ab = A  + (size_t)(by * 128) * K;
    const __half* Bb = Bt + (size_t)(bx * 256) * K;
    const int S = K >> 6;

    const int lr = tid >> 3;     // 0..31
    const int lc = tid & 7;      // chunk 0..7

    auto issue = [&](int s, int st) {
        const int k0 = s * 64;
        const uint32_t ao = sA + st * 16384;
        const uint32_t bo = sB + st * 32768;
        #pragma unroll
        for (int t = 0; t < 4; t++) {          // A: 128 rows
            int r = lr + t * 32;
            cp_async16(ao + HXS(r, lc), Ab + (size_t)r * K + k0 + lc * 8);
        }
        #pragma unroll
        for (int t = 0; t < 8; t++) {          // B: 256 rows
            int r = lr + t * 32;
            cp_async16(bo + HXS(r, lc), Bb + (size_t)r * K + k0 + lc * 8);
        }
        CP_COMMIT();
    };

    float acc[4][8][4];
    #pragma unroll
    for (int i = 0; i < 4; i++)
        #pragma unroll
        for (int j = 0; j < 8; j++)
            #pragma unroll
            for (int k = 0; k < 4; k++) acc[i][j][k] = 0.f;

    const int wm = (wid & 1) * 64;    // warp M offset: 0/64
    const int wn = (wid >> 1) * 64;   // warp N offset: 0/64/128/192
    const int g  = lane >> 2;
    const int tg = lane & 3;
    const int rr  = lane & 7;
    const int sub = lane >> 3;

    uint32_t aRowOff[4], aMask[4];
    const int khalfA = sub >> 1;
    #pragma unroll
    for (int mt = 0; mt < 4; mt++) {
        int row = wm + mt * 16 + (sub & 1) * 8 + rr;
        aRowOff[mt] = (uint32_t)(row * 128);
        aMask[mt]   = (uint32_t)(row & 7);
    }
    uint32_t bRowOff[4], bMask[4];
    const int khalfB = sub & 1;
    #pragma unroll
    for (int ntp = 0; ntp < 4; ntp++) {
        int row = wn + ntp * 16 + (sub >> 1) * 8 + rr;
        bRowOff[ntp] = (uint32_t)(row * 128);
        bMask[ntp]   = (uint32_t)(row & 7);
    }

    issue(0, 0);
    issue(1, 1);

    for (int s = 0; s < S; s++) {
        if (s + 1 < S) { CP_WAIT(1); } else { CP_WAIT(0); }
        __syncthreads();
        if (s + 2 < S) issue(s + 2, (s + 2) % 3);

        const uint32_t aBase = sA + (s % 3) * 16384;
        const uint32_t bBase = sB + (s % 3) * 32768;
        #pragma unroll
        for (int kk = 0; kk < 4; kk++) {
            uint32_t a[4][4], b[8][2];
            #pragma unroll
            for (int mt = 0; mt < 4; mt++) {
                uint32_t addr = aBase + aRowOff[mt]
                              + (((uint32_t)(kk * 2 + khalfA) ^ aMask[mt]) << 4);
                LDMX4(a[mt][0], a[mt][1], a[mt][2], a[mt][3], addr);
            }
            #pragma unroll
            for (int ntp = 0; ntp < 4; ntp++) {
                uint32_t addr = bBase + bRowOff[ntp]
                              + (((uint32_t)(kk * 2 + khalfB) ^ bMask[ntp]) << 4);
                LDMX4(b[ntp * 2][0], b[ntp * 2][1], b[ntp * 2 + 1][0], b[ntp * 2 + 1][1], addr);
            }
            #pragma unroll
            for (int mt = 0; mt < 4; mt++)
                #pragma unroll
                for (int nt = 0; nt < 8; nt++)
                    mma_f16(acc[mt][nt], a[mt], b[nt]);
        }
        __syncthreads();
    }

    // ---- epilogue ----
    #pragma unroll
    for (int mt = 0; mt < 4; mt++) {
        #pragma unroll
        for (int hh = 0; hh < 2; hh++) {
            const int row = by * 128 + wm + mt * 16 + g + hh * 8;
            const float* Rr = RES ? (res + (size_t)row * N) : (const float*)0;
            #pragma unroll
            for (int nt = 0; nt < 8; nt++) {
                const int col = bx * 256 + wn + nt * 8 + tg * 2;
                float v0 = acc[mt][nt][hh * 2 + 0];
                float v1 = acc[mt][nt][hh * 2 + 1];
                if (BIAS) { v0 += bias[col]; v1 += bias[col + 1]; }
                if (GELU) {
                    v0 = 0.5f * v0 * (1.f + erff(v0 * 0.70710678118654752f));
                    v1 = 0.5f * v1 * (1.f + erff(v1 * 0.70710678118654752f));
                }
                if (RES) { v0 += Rr[col]; v1 += Rr[col + 1]; }
                if (OUTH) {
                    __half2* Ch = (__half2*)((__half*)Cv + (size_t)row * N + col);
                    *Ch = __floats2half2_rn(v0, v1);
                } else {
                    float2* Cf = (float2*)((float*)Cv + (size_t)row * N + col);
                    *Cf = make_float2(v0, v1);
                }
            }
        }
    }
}

// ---------------------------------------------------------------------------
// fp16 flash attention (unchanged from round 8)
// ---------------------------------------------------------------------------
#define ATT_SMEM 40960
#define NKV      (SEQ / 32)

__global__ __launch_bounds__(256) void fattn(
    const __half* __restrict__ qkv, __half* __restrict__ out)
{
    extern __shared__ __align__(1024) char sm[];
    const uint32_t sb = smem_u32(sm);
    const uint32_t QOFF = 0, KOFF = 16384, VOFF = 28672;

    const int tid = threadIdx.x, wid = tid >> 5, lane = tid & 31;
    const int g = lane >> 2, tg = lane & 3;
    const int rr = lane & 7, sub = lane >> 3;
    const int wm = wid * 16;
    const int qb = blockIdx.x, h = blockIdx.y, b = blockIdx.z;
    const size_t tok0 = (size_t)b * SEQ + (size_t)qb * 128;
    const __half* qbase = qkv + tok0 * (3 * DM) + h * DH;

    #pragma unroll
    for (int t = 0; t < 4; t++) {
        int idx = tid + t * 256;
        int r = idx >> 3, c = idx & 7;
        cp_async16(sb + QOFF + HXS(r, c), qbase + (size_t)r * (3 * DM) + c * 8);
    }
    auto issue_kv = [&](int it) {
        const int buf = it % 3;
        const uint32_t base = sb + (tid < 128 ? KOFF : VOFF) + buf * 4096;
        const int seg = (tid < 128 ? DM : 2 * DM);
        #pragma unroll
        for (int t = 0; t < 2; t++) {
            const int chunk = (tid & 127) + t * 128;
            const int r = chunk >> 3, c = chunk & 7;
            cp_async16(base + HXS(r, c),
                       qkv + ((size_t)b * SEQ + it * 32 + r) * (3 * DM) + seg + h * DH + c * 8);
        }
        CP_COMMIT();
    };
    issue_kv(0);
    issue_kv(1);
    issue_kv(2);

    CP_WAIT(2);
    __syncthreads();

    uint32_t qf[4][4];
    {
        const int row = wm + (sub & 1) * 8 + rr;
        const uint32_t rowOff = (uint32_t)(row * 128);
        const uint32_t mask = (uint32_t)(row & 7);
        const int khalf = sub >> 1;
        #pragma unroll
        for (int kk = 0; kk < 4; kk++) {
            uint32_t addr = sb + QOFF + rowOff + (((uint32_t)(kk * 2 + khalf) ^ mask) << 4);
            LDMX4(qf[kk][0], qf[kk][1], qf[kk][2], qf[kk][3], addr);
        }
    }

    float oa[8][4];
    #pragma unroll
    for (int i = 0; i < 8; i++)
        #pragma unroll
        for (int j = 0; j < 4; j++) oa[i][j] = 0.f;
    float m0 = -1e30f, m1 = -1e30f, l0 = 0.f, l1 = 0.f;

    const int kRow = (sub >> 1) * 8 + rr;
    const int kHalf = sub & 1;

    for (int it = 0; it < NKV; it++) {
        if (it < NKV - 2)      { CP_WAIT(2); }
        else if (it == NKV - 2){ CP_WAIT(1); }
        else                   { CP_WAIT(0); }
        __syncthreads();

        const int buf = it % 3;
        const uint32_t kbuf = sb + KOFF + buf * 4096;
        const uint32_t vbuf = sb + VOFF + buf * 4096;

        float sf[4][4];
        #pragma unroll
        for (int nt = 0; nt < 4; nt++)
            #pragma unroll
            for (int e = 0; e < 4; e++) sf[nt][e] = 0.f;

        #pragma unroll
        for (int kk = 0; kk < 4; kk++) {
            uint32_t bfr[4][2];
            #pragma unroll
            for (int ntp = 0; ntp < 2; ntp++) {
                const int row = ntp * 16 + kRow;
                uint32_t addr = kbuf + (uint32_t)(row * 128)
                              + (((uint32_t)(kk * 2 + kHalf) ^ (uint32_t)(row & 7)) << 4);
                LDMX4(bfr[ntp * 2][0], bfr[ntp * 2][1],
                      bfr[ntp * 2 + 1][0], bfr[ntp * 2 + 1][1], addr);
            }
            #pragma unroll
            for (int nt = 0; nt < 4; nt++)
                mma_f16(sf[nt], qf[kk], bfr[nt]);
        }

        float mx0 = -1e30f, mx1 = -1e30f;
        #pragma unroll
        for (int nt = 0; nt < 4; nt++) {
            #pragma unroll
            for (int e = 0; e < 4; e++) sf[nt][e] *= 0.125f;
            mx0 = fmaxf(mx0, fmaxf(sf[nt][0], sf[nt][1]));
            mx1 = fmaxf(mx1, fmaxf(sf[nt][2], sf[nt][3]));
        }
        mx0 = fmaxf(mx0, __shfl_xor_sync(0xffffffffu, mx0, 1));
        mx0 = fmaxf(mx0, __shfl_xor_sync(0xffffffffu, mx0, 2));
        mx1 = fmaxf(mx1, __shfl_xor_sync(0xffffffffu, mx1, 1));
        mx1 = fmaxf(mx1, __shfl_xor_sync(0xffffffffu, mx1, 2));
        const float nm0 = fmaxf(m0, mx0), nm1 = fmaxf(m1, mx1);
        const float cr0 = __expf(m0 - nm0), cr1 = __expf(m1 - nm1);
        m0 = nm0; m1 = nm1;

        float ls0 = 0.f, ls1 = 0.f;
        #pragma unroll
        for (int nt = 0; nt < 4; nt++) {
            sf[nt][0] = __expf(sf[nt][0] - m0);
            sf[nt][1] = __expf(sf[nt][1] - m0);
            sf[nt][2] = __expf(sf[nt][2] - m1);
            sf[nt][3] = __expf(sf[nt][3] - m1);
            ls0 += sf[nt][0] + sf[nt][1];
            ls1 += sf[nt][2] + sf[nt][3];
        }
        ls0 += __shfl_xor_sync(0xffffffffu, ls0, 1);
        ls0 += __shfl_xor_sync(0xffffffffu, ls0, 2);
        ls1 += __shfl_xor_sync(0xffffffffu, ls1, 1);
        ls1 += __shfl_xor_sync(0xffffffffu, ls1, 2);
        l0 = l0 * cr0 + ls0;
        l1 = l1 * cr1 + ls1;

        #pragma unroll
        for (int nt = 0; nt < 8; nt++) {
            oa[nt][0] *= cr0; oa[nt][1] *= cr0;
            oa[nt][2] *= cr1; oa[nt][3] *= cr1;
        }

        #pragma unroll
        for (int kk = 0; kk < 2; kk++) {
            uint32_t a[4];
            a[0] = packh2(sf[kk * 2][0],     sf[kk * 2][1]);
            a[1] = packh2(sf[kk * 2][2],     sf[kk * 2][3]);
            a[2] = packh2(sf[kk * 2 + 1][0], sf[kk * 2 + 1][1]);
            a[3] = packh2(sf[kk * 2 + 1][2], sf[kk * 2 + 1][3]);
            const int key = kk * 16 + (sub & 1) * 8 + rr;
            const uint32_t keyOff = (uint32_t)(key * 128);
            const uint32_t keyMask = (uint32_t)(key & 7);
            #pragma unroll
            for (int ntp = 0; ntp < 4; ntp++) {
                uint32_t b0[2], b1[2];
                uint32_t addr = vbuf + keyOff
                              + (((uint32_t)(ntp * 2 + (sub >> 1)) ^ keyMask) << 4);
                LDMX4T(b0[0], b0[1], b1[0], b1[1], addr);
                mma_f16(oa[ntp * 2],     a, b0);
                mma_f16(oa[ntp * 2 + 1], a, b1);
            }
        }
        __syncthreads();
        if (it + 3 < NKV) issue_kv(it + 3);
    }

    const float inv0 = 1.f / l0, inv1 = 1.f / l1;
    #pragma unroll
    for (int nt = 0; nt < 8; nt++) {
        const int col = h * DH + nt * 8 + 2 * tg;
        __half* o0 = out + (tok0 + wm + g) * DM + col;
        __half* o1 = out + (tok0 + wm + g + 8) * DM + col;
        *(__half2*)o0 = __floats2half2_rn(oa[nt][0] * inv0, oa[nt][1] * inv0);
        *(__half2*)o1 = __floats2half2_rn(oa[nt][2] * inv1, oa[nt][3] * inv1);
    }
}

// ---------------------------------------------------------------------------
// Weight transpose to fp16
// ---------------------------------------------------------------------------
__global__ __launch_bounds__(256) void transpose_h(
    const float* __restrict__ W, __half* __restrict__ Wt, int K, int N)
{
    __shared__ float t[32][33];
    int n0 = blockIdx.x * 32, k0 = blockIdx.y * 32;
    int tx = threadIdx.x & 31, ty = threadIdx.x >> 5;
    #pragma unroll
    for (int i = 0; i < 32; i += 8)
        t[ty + i][tx] = W[(size_t)(k0 + ty + i) * N + n0 + tx];
    __syncthreads();
    #pragma unroll
    for (int i = 0; i < 32; i += 8)
        Wt[(size_t)(n0 + ty + i) * K + k0 + tx] = __float2half_rn(t[tx][ty + i]);
}

__global__ void concat_bias(const float* __restrict__ b1, const float* __restrict__ b2,
                            float* __restrict__ o) {
    int i = blockIdx.x * blockDim.x + threadIdx.x;
    if (i < 2 * DM) o[i] = b1[i];
    else            o[i] = b2[i - 2 * DM];
}

// ---------------------------------------------------------------------------
// silu -> fp16
// ---------------------------------------------------------------------------
__global__ void silu_kernel(const float* __restrict__ in, __half* __restrict__ out, int n4) {
    int i = blockIdx.x * blockDim.x + threadIdx.x;
    if (i >= n4) return;
    float4 v = ((const float4*)in)[i];
    __half2 a = __floats2half2_rn(v.x / (1.f + expf(-v.x)), v.y / (1.f + expf(-v.y)));
    __half2 b = __floats2half2_rn(v.z / (1.f + expf(-v.z)), v.w / (1.f + expf(-v.w)));
    __half2* o = (__half2*)(out + (size_t)i * 4);
    o[0] = a; o[1] = b;
}

// ---------------------------------------------------------------------------
// AdaLN (gb in fp16 now) -> fp16
// ---------------------------------------------------------------------------
__global__ __launch_bounds__(256) void adaln_kernel(
    const float* __restrict__ x, const __half* __restrict__ gb, int gbStride,
    int gbOff, __half* __restrict__ out)
{
    int row = blockIdx.x;
    const float* xr = x + (size_t)row * DM;
    int i = threadIdx.x * 4;
    float4 v = *(const float4*)(xr + i);
    float s  = v.x + v.y + v.z + v.w;
    float ss = v.x*v.x + v.y*v.y + v.z*v.z + v.w*v.w;
    #pragma unroll
    for (int o = 16; o > 0; o >>= 1) {
        s  += __shfl_xor_sync(0xffffffffu, s,  o);
        ss += __shfl_xor_sync(0xffffffffu, ss, o);
    }
    __shared__ float sh[16];
    int w = threadIdx.x >> 5, ln = threadIdx.x & 31;
    if (ln == 0) { sh[w] = s; sh[w + 8] = ss; }
    __syncthreads();
    float fs = 0.f, fss = 0.f;
    #pragma unroll
    for (int k = 0; k < 8; k++) { fs += sh[k]; fss += sh[k + 8]; }
    float mu   = fs  * (1.f / DM);
    float var  = fss * (1.f / DM) - mu * mu;
    float rstd = rsqrtf(var + 1e-5f);

    const __half* gp = gb + (size_t)row * gbStride + gbOff;
    __half2 ga01 = *(const __half2*)(gp + i);
    __half2 ga23 = *(const __half2*)(gp + i + 2);
    __half2 be01 = *(const __half2*)(gp + DM + i);
    __half2 be23 = *(const __half2*)(gp + DM + i + 2);
    float2 ga0 = __half22float2(ga01), ga1 = __half22float2(ga23);
    float2 be0 = __half22float2(be01), be1 = __half22float2(be23);
    float o0 = (v.x - mu) * rstd * (1.f + ga0.x) + be0.x;
    float o1 = (v.y - mu) * rstd * (1.f + ga0.y) + be0.y;
    float o2 = (v.z - mu) * rstd * (1.f + ga1.x) + be1.x;
    float o3 = (v.w - mu) * rstd * (1.f + ga1.y) + be1.y;
    __half2* op = (__half2*)(out + (size_t)row * DM + i);
    op[0] = __floats2half2_rn(o0, o1);
    op[1] = __floats2half2_rn(o2, o3);
}

// ---------------------------------------------------------------------------
// Launch
// ---------------------------------------------------------------------------
extern "C" void kernel_launch(void* const* d_in, const int* in_sizes, int n_in,
                              void* d_out, int out_size)
{
    const float* x          = (const float*)d_in[0];
    const float* cond       = (const float*)d_in[1];
    const float* p1_w       = (const float*)d_in[2];
    const float* p1_b       = (const float*)d_in[3];
    const float* qkv_w      = (const float*)d_in[4];
    const float* attn_out_w = (const float*)d_in[5];
    const float* p2_w       = (const float*)d_in[6];
    const float* p2_b       = (const float*)d_in[7];
    const float* ffn_w1     = (const float*)d_in[8];
    const float* ffn_b1     = (const float*)d_in[9];
    const float* ffn_w2     = (const float*)d_in[10];
    const float* ffn_b2     = (const float*)d_in[11];
    float* out = (float*)d_out;

    __half *sc, *h, *attn, *ff, *qkv, *gb;
    float *x2, *b_p12;
    __half *wt_p12, *wt_qkv, *wt_ao, *wt_f1, *wt_f2;
    cudaGetSymbolAddress((void**)&sc,     g_sc);
    cudaGetSymbolAddress((void**)&gb,     g_gb);
    cudaGetSymbolAddress((void**)&h,      g_h);
    cudaGetSymbolAddress((void**)&qkv,    g_qkv);
    cudaGetSymbolAddress((void**)&attn,   g_attn);
    cudaGetSymbolAddress((void**)&x2,     g_x2);
    cudaGetSymbolAddress((void**)&ff,     g_ff);
    cudaGetSymbolAddress((void**)&wt_p12, g_wt_p12);
    cudaGetSymbolAddress((void**)&wt_qkv, g_wt_qkv);
    cudaGetSymbolAddress((void**)&wt_ao,  g_wt_ao);
    cudaGetSymbolAddress((void**)&wt_f1,  g_wt_f1);
    cudaGetSymbolAddress((void**)&wt_f2,  g_wt_f2);
    cudaGetSymbolAddress((void**)&b_p12,  g_b_p12);

    cudaFuncSetAttribute(hgemm<1,0,0,1>, cudaFuncAttributeMaxDynamicSharedMemorySize, TG_SMEM);
    cudaFuncSetAttribute(hgemm<0,0,0,1>, cudaFuncAttributeMaxDynamicSharedMemorySize, TG_SMEM);
    cudaFuncSetAttribute(hgemm<0,0,1,0>, cudaFuncAttributeMaxDynamicSharedMemorySize, TG_SMEM);
    cudaFuncSetAttribute(hgemm<1,1,0,1>, cudaFuncAttributeMaxDynamicSharedMemorySize, TG_SMEM);
    cudaFuncSetAttribute(hgemm<1,0,1,0>, cudaFuncAttributeMaxDynamicSharedMemorySize, TG_SMEM);
    cudaFuncSetAttribute(fattn, cudaFuncAttributeMaxDynamicSharedMemorySize, ATT_SMEM);

    transpose_h<<<dim3(2048/32,  512/32), 256>>>(p1_w, wt_p12,              512, 2048);
    transpose_h<<<dim3(2048/32,  512/32), 256>>>(p2_w, wt_p12 + 2048 * 512, 512, 2048);
    transpose_h<<<dim3(3072/32, 1024/32), 256>>>(qkv_w,      wt_qkv, 1024, 3072);
    transpose_h<<<dim3(1024/32, 1024/32), 256>>>(attn_out_w, wt_ao,  1024, 1024);
    transpose_h<<<dim3(4096/32, 1024/32), 256>>>(ffn_w1,     wt_f1,  1024, 4096);
    transpose_h<<<dim3(1024/32, 4096/32), 256>>>(ffn_w2,     wt_f2,  4096, 1024);
    concat_bias<<<(4 * DM + 255) / 256, 256>>>(p1_b, p2_b, b_p12);

    // 1. sc = silu(cond) -> fp16
    silu_kernel<<<(BS_TOK * DC / 4 + 255) / 256, 256>>>(cond, sc, BS_TOK * DC / 4);
    // 2. gb = sc @ [p1|p2] + bias -> fp16   (M=4096, N=4096, K=512)
    hgemm<1,0,0,1><<<dim3(4096/256, BS_TOK/128), 256, TG_SMEM>>>(
        sc, wt_p12, b_p12, nullptr, gb, BS_TOK, 4096, DC);
    // 3. h = adaln(x, gb[:, 0:2048]) -> fp16
    adaln_kernel<<<BS_TOK, 256>>>(x, gb, 4096, 0, h);
    // 4. qkv = h @ qkv_w -> fp16
    hgemm<0,0,0,1><<<dim3(3072/256, BS_TOK/128), 256, TG_SMEM>>>(
        h, wt_qkv, nullptr, nullptr, qkv, BS_TOK, 3072, DM);
    // 5. attention -> fp16
    fattn<<<dim3(SEQ/128, NH, 2), 256, ATT_SMEM>>>(qkv, attn);
    // 6. x2 = x + attn @ attn_out_w (fp32 out)
    hgemm<0,0,1,0><<<dim3(1024/256, BS_TOK/128), 256, TG_SMEM>>>(
        attn, wt_ao, nullptr, x, x2, BS_TOK, 1024, DM);
    // 7. h = adaln(x2, gb[:, 2048:4096]) -> fp16
    adaln_kernel<<<BS_TOK, 256>>>(x2, gb, 4096, 2048, h);
    // 8. ff = gelu(h @ ffn_w1 + ffn_b1) -> fp16
    hgemm<1,1,0,1><<<dim3(DFF/256, BS_TOK/128), 256, TG_SMEM>>>(
        h, wt_f1, ffn_b1, nullptr, ff, BS_TOK, DFF, DM);
    // 9. out = x2 + ff @ ffn_w2 + ffn_b2 (fp32 out)
    hgemm<1,0,1,0><<<dim3(1024/256, BS_TOK/128), 256, TG_SMEM>>>(
        ff, wt_f2, ffn_b2, x2, out, BS_TOK, 1024, DFF);
}

// round 16
// speedup vs baseline: 1.0883x; 1.0883x over previous
#include <cuda_runtime.h>
#include <cuda_fp16.h>
#include <math.h>
#include <stdint.h>

// ---------------------------------------------------------------------------
// DecoderBlock: B=2, S=2048, D_MODEL=1024, D_COND=512, H=16, d=64, FF=4096
// Round 13: revert hgemm to 128x128/2-CTA (R11), drop redundant mainloop
// barrier, fast 64x64 transpose. Keep fp16 gb + merged p1|p2 GEMM.
// ---------------------------------------------------------------------------

#define BS_TOK   4096
#define DM       1024
#define DC       512
#define DFF      4096
#define NH       16
#define DH       64
#define SEQ      2048

// ---------------- scratch ---------------------------------------------------
__device__ __half g_sc  [BS_TOK * DC];
__device__ __half g_gb  [BS_TOK * 4 * DM];   // merged gamma/beta, fp16
__device__ __half g_h   [BS_TOK * DM];
__device__ __half g_qkv [BS_TOK * 3 * DM];
__device__ __half g_attn[BS_TOK * DM];
__device__ float  g_x2  [BS_TOK * DM];
__device__ __half g_ff  [BS_TOK * DFF];
__device__ __half g_wt_p12[4 * DM * DC];
__device__ __half g_wt_qkv[3 * DM * DM];
__device__ __half g_wt_ao [DM * DM];
__device__ __half g_wt_f1 [DFF * DM];
__device__ __half g_wt_f2 [DM * DFF];
__device__ float  g_b_p12 [4 * DM];

// ---------------- helpers ---------------------------------------------------
__device__ __forceinline__ uint32_t smem_u32(const void* p) {
    uint32_t a;
    asm("{ .reg .u64 t; cvta.to.shared.u64 t, %1; cvt.u32.u64 %0, t; }"
        : "=r"(a) : "l"(p));
    return a;
}
__device__ __forceinline__ void cp_async16(uint32_t dst, const void* src) {
    asm volatile("cp.async.cg.shared.global [%0], [%1], 16;"
                 :: "r"(dst), "l"(src) : "memory");
}
#define CP_COMMIT() asm volatile("cp.async.commit_group;" ::: "memory")
#define CP_WAIT(n)  asm volatile("cp.async.wait_group %0;" :: "n"(n) : "memory")

__device__ __forceinline__ void mma_f16(float* c, const uint32_t* a, const uint32_t* b) {
    asm volatile("mma.sync.aligned.m16n8k16.row.col.f32.f16.f16.f32 "
        "{%0,%1,%2,%3}, {%4,%5,%6,%7}, {%8,%9}, {%0,%1,%2,%3};"
        : "+f"(c[0]), "+f"(c[1]), "+f"(c[2]), "+f"(c[3])
        : "r"(a[0]), "r"(a[1]), "r"(a[2]), "r"(a[3]), "r"(b[0]), "r"(b[1]));
}
#define LDMX4(r0, r1, r2, r3, addr)                                           \
    asm volatile("ldmatrix.sync.aligned.m8n8.x4.shared.b16 {%0,%1,%2,%3}, [%4];" \
        : "=r"(r0), "=r"(r1), "=r"(r2), "=r"(r3) : "r"(addr))
#define LDMX4T(r0, r1, r2, r3, addr)                                          \
    asm volatile("ldmatrix.sync.aligned.m8n8.x4.trans.shared.b16 {%0,%1,%2,%3}, [%4];" \
        : "=r"(r0), "=r"(r1), "=r"(r2), "=r"(r3) : "r"(addr))

__device__ __forceinline__ uint32_t packh2(float x, float y) {
    __half2 h = __floats2half2_rn(x, y);
    return *(uint32_t*)&h;
}

#define HXS(r, c) ((uint32_t)((r) * 128 + (((c) ^ ((r) & 7)) << 4)))

// ---------------------------------------------------------------------------
// fp16 mma GEMM: C[M,N] = A[M,K] @ Bt[N,K]^T (+bias)(+gelu)(+res)
// BM=BN=128, BK=64, 3-stage cp.async, 256 threads, 2 CTAs/SM.
// Single barrier per stage (top sync after CP_WAIT protects buffer reuse).
// ---------------------------------------------------------------------------
#define TG_SMEM 98304

template<int BIAS, int GELU, int RES, int OUTH>
__global__ __launch_bounds__(256, 2) void hgemm(
    const __half* __restrict__ A, const __half* __restrict__ Bt,
    const float* __restrict__ bias, const float* __restrict__ res,
    void* __restrict__ Cv, int M, int N, int K)
{
    extern __shared__ __align__(1024) char smem_raw[];
    const uint32_t sA = smem_u32(smem_raw);
    const uint32_t sB = sA + 3 * 16384;

    const int tid  = threadIdx.x;
    const int wid  = tid >> 5;
    const int lane = tid & 31;
    const int bx = blockIdx.x, by = blockIdx.y;

    const __half* Ab = A  + (size_t)(by * 128) * K;
    const __half* Bb = Bt + (size_t)(bx * 128) * K;
    const int S = K >> 6;

    const int lr = tid >> 3;
    const int lc = tid & 7;

    auto issue = [&](int s, int st) {
        const int k0 = s * 64;
        const uint32_t ao = sA + st * 16384;
        const uint32_t bo = sB + st * 16384;
        #pragma unroll
        for (int t = 0; t < 4; t++) {
            int r = lr + t * 32;
            uint32_t off = HXS(r, lc);
            cp_async16(ao + off, Ab + (size_t)r * K + k0 + lc * 8);
            cp_async16(bo + off, Bb + (size_t)r * K + k0 + lc * 8);
        }
        CP_COMMIT();
    };

    float acc[4][4][4];
    #pragma unroll
    for (int i = 0; i < 4; i++)
        #pragma unroll
        for (int j = 0; j < 4; j++)
            #pragma unroll
            for (int k = 0; k < 4; k++) acc[i][j][k] = 0.f;

    const int wm = (wid >> 2) * 64;
    const int wn = (wid & 3) * 32;
    const int g  = lane >> 2;
    const int tg = lane & 3;
    const int rr  = lane & 7;
    const int sub = lane >> 3;

    uint32_t aRowOff[4], aMask[4];
    const int khalfA = sub >> 1;
    #pragma unroll
    for (int mt = 0; mt < 4; mt++) {
        int row = wm + mt * 16 + (sub & 1) * 8 + rr;
        aRowOff[mt] = (uint32_t)(row * 128);
        aMask[mt]   = (uint32_t)(row & 7);
    }
    uint32_t bRowOff[2], bMask[2];
    const int khalfB = sub & 1;
    #pragma unroll
    for (int ntp = 0; ntp < 2; ntp++) {
        int row = wn + (ntp * 2 + (sub >> 1)) * 8 + rr;
        bRowOff[ntp] = (uint32_t)(row * 128);
        bMask[ntp]   = (uint32_t)(row & 7);
    }

    issue(0, 0);
    issue(1, 1);

    for (int s = 0; s < S; s++) {
        if (s + 1 < S) { CP_WAIT(1); } else { CP_WAIT(0); }
        __syncthreads();   // all warps finished compute(s-1); buffers safe
        if (s + 2 < S) issue(s + 2, (s + 2) % 3);

        const uint32_t aBase = sA + (s % 3) * 16384;
        const uint32_t bBase = sB + (s % 3) * 16384;
        #pragma unroll
        for (int kk = 0; kk < 4; kk++) {
            uint32_t a[4][4], b[4][2];
            #pragma unroll
            for (int mt = 0; mt < 4; mt++) {
                uint32_t addr = aBase + aRowOff[mt]
                              + (((uint32_t)(kk * 2 + khalfA) ^ aMask[mt]) << 4);
                LDMX4(a[mt][0], a[mt][1], a[mt][2], a[mt][3], addr);
            }
            #pragma unroll
            for (int ntp = 0; ntp < 2; ntp++) {
                uint32_t addr = bBase + bRowOff[ntp]
                              + (((uint32_t)(kk * 2 + khalfB) ^ bMask[ntp]) << 4);
                LDMX4(b[ntp * 2][0], b[ntp * 2][1], b[ntp * 2 + 1][0], b[ntp * 2 + 1][1], addr);
            }
            #pragma unroll
            for (int mt = 0; mt < 4; mt++)
                #pragma unroll
                for (int nt = 0; nt < 4; nt++)
                    mma_f16(acc[mt][nt], a[mt], b[nt]);
        }
        // no bottom barrier: next iteration's top barrier provides the hazard fence
    }

    #pragma unroll
    for (int mt = 0; mt < 4; mt++) {
        #pragma unroll
        for (int hh = 0; hh < 2; hh++) {
            const int row = by * 128 + wm + mt * 16 + g + hh * 8;
            const float* Rr = RES ? (res + (size_t)row * N) : (const float*)0;
            #pragma unroll
            for (int nt = 0; nt < 4; nt++) {
                const int col = bx * 128 + wn + nt * 8 + tg * 2;
                float v0 = acc[mt][nt][hh * 2 + 0];
                float v1 = acc[mt][nt][hh * 2 + 1];
                if (BIAS) { v0 += bias[col]; v1 += bias[col + 1]; }
                if (GELU) {
                    v0 = 0.5f * v0 * (1.f + erff(v0 * 0.70710678118654752f));
                    v1 = 0.5f * v1 * (1.f + erff(v1 * 0.70710678118654752f));
                }
                if (RES) { v0 += Rr[col]; v1 += Rr[col + 1]; }
                if (OUTH) {
                    __half2* Ch = (__half2*)((__half*)Cv + (size_t)row * N + col);
                    *Ch = __floats2half2_rn(v0, v1);
                } else {
                    float2* Cf = (float2*)((float*)Cv + (size_t)row * N + col);
                    *Cf = make_float2(v0, v1);
                }
            }
        }
    }
}

// ---------------------------------------------------------------------------
// fp16 flash attention (unchanged)
// ---------------------------------------------------------------------------
#define ATT_SMEM 40960
#define NKV      (SEQ / 32)

__global__ __launch_bounds__(256) void fattn(
    const __half* __restrict__ qkv, __half* __restrict__ out)
{
    extern __shared__ __align__(1024) char sm[];
    const uint32_t sb = smem_u32(sm);
    const uint32_t QOFF = 0, KOFF = 16384, VOFF = 28672;

    const int tid = threadIdx.x, wid = tid >> 5, lane = tid & 31;
    const int g = lane >> 2, tg = lane & 3;
    const int rr = lane & 7, sub = lane >> 3;
    const int wm = wid * 16;
    const int qb = blockIdx.x, h = blockIdx.y, b = blockIdx.z;
    const size_t tok0 = (size_t)b * SEQ + (size_t)qb * 128;
    const __half* qbase = qkv + tok0 * (3 * DM) + h * DH;

    #pragma unroll
    for (int t = 0; t < 4; t++) {
        int idx = tid + t * 256;
        int r = idx >> 3, c = idx & 7;
        cp_async16(sb + QOFF + HXS(r, c), qbase + (size_t)r * (3 * DM) + c * 8);
    }
    auto issue_kv = [&](int it) {
        const int buf = it % 3;
        const uint32_t base = sb + (tid < 128 ? KOFF : VOFF) + buf * 4096;
        const int seg = (tid < 128 ? DM : 2 * DM);
        #pragma unroll
        for (int t = 0; t < 2; t++) {
            const int chunk = (tid & 127) + t * 128;
            const int r = chunk >> 3, c = chunk & 7;
            cp_async16(base + HXS(r, c),
                       qkv + ((size_t)b * SEQ + it * 32 + r) * (3 * DM) + seg + h * DH + c * 8);
        }
        CP_COMMIT();
    };
    issue_kv(0);
    issue_kv(1);
    issue_kv(2);

    CP_WAIT(2);
    __syncthreads();

    uint32_t qf[4][4];
    {
        const int row = wm + (sub & 1) * 8 + rr;
        const uint32_t rowOff = (uint32_t)(row * 128);
        const uint32_t mask = (uint32_t)(row & 7);
        const int khalf = sub >> 1;
        #pragma unroll
        for (int kk = 0; kk < 4; kk++) {
            uint32_t addr = sb + QOFF + rowOff + (((uint32_t)(kk * 2 + khalf) ^ mask) << 4);
            LDMX4(qf[kk][0], qf[kk][1], qf[kk][2], qf[kk][3], addr);
        }
    }

    float oa[8][4];
    #pragma unroll
    for (int i = 0; i < 8; i++)
        #pragma unroll
        for (int j = 0; j < 4; j++) oa[i][j] = 0.f;
    float m0 = -1e30f, m1 = -1e30f, l0 = 0.f, l1 = 0.f;

    const int kRow = (sub >> 1) * 8 + rr;
    const int kHalf = sub & 1;

    for (int it = 0; it < NKV; it++) {
        if (it < NKV - 2)      { CP_WAIT(2); }
        else if (it == NKV - 2){ CP_WAIT(1); }
        else                   { CP_WAIT(0); }
        __syncthreads();

        const int buf = it % 3;
        const uint32_t kbuf = sb + KOFF + buf * 4096;
        const uint32_t vbuf = sb + VOFF + buf * 4096;

        float sf[4][4];
        #pragma unroll
        for (int nt = 0; nt < 4; nt++)
            #pragma unroll
            for (int e = 0; e < 4; e++) sf[nt][e] = 0.f;

        #pragma unroll
        for (int kk = 0; kk < 4; kk++) {
            uint32_t bfr[4][2];
            #pragma unroll
            for (int ntp = 0; ntp < 2; ntp++) {
                const int row = ntp * 16 + kRow;
                uint32_t addr = kbuf + (uint32_t)(row * 128)
                              + (((uint32_t)(kk * 2 + kHalf) ^ (uint32_t)(row & 7)) << 4);
                LDMX4(bfr[ntp * 2][0], bfr[ntp * 2][1],
                      bfr[ntp * 2 + 1][0], bfr[ntp * 2 + 1][1], addr);
            }
            #pragma unroll
            for (int nt = 0; nt < 4; nt++)
                mma_f16(sf[nt], qf[kk], bfr[nt]);
        }

        float mx0 = -1e30f, mx1 = -1e30f;
        #pragma unroll
        for (int nt = 0; nt < 4; nt++) {
            #pragma unroll
            for (int e = 0; e < 4; e++) sf[nt][e] *= 0.125f;
            mx0 = fmaxf(mx0, fmaxf(sf[nt][0], sf[nt][1]));
            mx1 = fmaxf(mx1, fmaxf(sf[nt][2], sf[nt][3]));
        }
        mx0 = fmaxf(mx0, __shfl_xor_sync(0xffffffffu, mx0, 1));
        mx0 = fmaxf(mx0, __shfl_xor_sync(0xffffffffu, mx0, 2));
        mx1 = fmaxf(mx1, __shfl_xor_sync(0xffffffffu, mx1, 1));
        mx1 = fmaxf(mx1, __shfl_xor_sync(0xffffffffu, mx1, 2));
        const float nm0 = fmaxf(m0, mx0), nm1 = fmaxf(m1, mx1);
        const float cr0 = __expf(m0 - nm0), cr1 = __expf(m1 - nm1);
        m0 = nm0; m1 = nm1;

        float ls0 = 0.f, ls1 = 0.f;
        #pragma unroll
        for (int nt = 0; nt < 4; nt++) {
            sf[nt][0] = __expf(sf[nt][0] - m0);
            sf[nt][1] = __expf(sf[nt][1] - m0);
            sf[nt][2] = __expf(sf[nt][2] - m1);
            sf[nt][3] = __expf(sf[nt][3] - m1);
            ls0 += sf[nt][0] + sf[nt][1];
            ls1 += sf[nt][2] + sf[nt][3];
        }
        ls0 += __shfl_xor_sync(0xffffffffu, ls0, 1);
        ls0 += __shfl_xor_sync(0xffffffffu, ls0, 2);
        ls1 += __shfl_xor_sync(0xffffffffu, ls1, 1);
        ls1 += __shfl_xor_sync(0xffffffffu, ls1, 2);
        l0 = l0 * cr0 + ls0;
        l1 = l1 * cr1 + ls1;

        #pragma unroll
        for (int nt = 0; nt < 8; nt++) {
            oa[nt][0] *= cr0; oa[nt][1] *= cr0;
            oa[nt][2] *= cr1; oa[nt][3] *= cr1;
        }

        #pragma unroll
        for (int kk = 0; kk < 2; kk++) {
            uint32_t a[4];
            a[0] = packh2(sf[kk * 2][0],     sf[kk * 2][1]);
            a[1] = packh2(sf[kk * 2][2],     sf[kk * 2][3]);
            a[2] = packh2(sf[kk * 2 + 1][0], sf[kk * 2 + 1][1]);
            a[3] = packh2(sf[kk * 2 + 1][2], sf[kk * 2 + 1][3]);
            const int key = kk * 16 + (sub & 1) * 8 + rr;
            const uint32_t keyOff = (uint32_t)(key * 128);
            const uint32_t keyMask = (uint32_t)(key & 7);
            #pragma unroll
            for (int ntp = 0; ntp < 4; ntp++) {
                uint32_t b0[2], b1[2];
                uint32_t addr = vbuf + keyOff
                              + (((uint32_t)(ntp * 2 + (sub >> 1)) ^ keyMask) << 4);
                LDMX4T(b0[0], b0[1], b1[0], b1[1], addr);
                mma_f16(oa[ntp * 2],     a, b0);
                mma_f16(oa[ntp * 2 + 1], a, b1);
            }
        }
        __syncthreads();
        if (it + 3 < NKV) issue_kv(it + 3);
    }

    const float inv0 = 1.f / l0, inv1 = 1.f / l1;
    #pragma unroll
    for (int nt = 0; nt < 8; nt++) {
        const int col = h * DH + nt * 8 + 2 * tg;
        __half* o0 = out + (tok0 + wm + g) * DM + col;
        __half* o1 = out + (tok0 + wm + g + 8) * DM + col;
        *(__half2*)o0 = __floats2half2_rn(oa[nt][0] * inv0, oa[nt][1] * inv0);
        *(__half2*)o1 = __floats2half2_rn(oa[nt][2] * inv1, oa[nt][3] * inv1);
    }
}

// ---------------------------------------------------------------------------
// Weight transpose to fp16: 64x64 tiles, float4 loads, __half2 stores.
// ---------------------------------------------------------------------------
__global__ __launch_bounds__(256) void transpose_h(
    const float* __restrict__ W, __half* __restrict__ Wt, int K, int N)
{
    __shared__ float t[64][65];
    const int n0 = blockIdx.x * 64, k0 = blockIdx.y * 64;
    const int tc = threadIdx.x & 15;   // float4 col 0..15
    const int tr = threadIdx.x >> 4;   // row 0..15
    #pragma unroll
    for (int i = 0; i < 4; i++) {
        int k = tr + i * 16;
        float4 v = *(const float4*)(W + (size_t)(k0 + k) * N + n0 + tc * 4);
        t[k][tc * 4 + 0] = v.x; t[k][tc * 4 + 1] = v.y;
        t[k][tc * 4 + 2] = v.z; t[k][tc * 4 + 3] = v.w;
    }
    __syncthreads();
    const int k2 = (threadIdx.x & 31) * 2;
    const int nr = threadIdx.x >> 5;   // 0..7
    #pragma unroll
    for (int j = 0; j < 8; j++) {
        int n = nr + j * 8;
        __half2 h = __floats2half2_rn(t[k2][n], t[k2 + 1][n]);
        *(__half2*)(Wt + (size_t)(n0 + n) * K + k0 + k2) = h;
    }
}

__global__ void concat_bias(const float* __restrict__ b1, const float* __restrict__ b2,
                            float* __restrict__ o) {
    int i = blockIdx.x * blockDim.x + threadIdx.x;
    if (i < 2 * DM) o[i] = b1[i];
    else            o[i] = b2[i - 2 * DM];
}

// ---------------------------------------------------------------------------
// silu -> fp16
// ---------------------------------------------------------------------------
__global__ void silu_kernel(const float* __restrict__ in, __half* __restrict__ out, int n4) {
    int i = blockIdx.x * blockDim.x + threadIdx.x;
    if (i >= n4) return;
    float4 v = ((const float4*)in)[i];
    __half2 a = __floats2half2_rn(v.x / (1.f + expf(-v.x)), v.y / (1.f + expf(-v.y)));
    __half2 b = __floats2half2_rn(v.z / (1.f + expf(-v.z)), v.w / (1.f + expf(-v.w)));
    __half2* o = (__half2*)(out + (size_t)i * 4);
    o[0] = a; o[1] = b;
}

// ---------------------------------------------------------------------------
// AdaLN (gb fp16) -> fp16
// ---------------------------------------------------------------------------
__global__ __launch_bounds__(256) void adaln_kernel(
    const float* __restrict__ x, const __half* __restrict__ gb, int gbStride,
    int gbOff, __half* __restrict__ out)
{
    int row = blockIdx.x;
    const float* xr = x + (size_t)row * DM;
    int i = threadIdx.x * 4;
    float4 v = *(const float4*)(xr + i);
    float s  = v.x + v.y + v.z + v.w;
    float ss = v.x*v.x + v.y*v.y + v.z*v.z + v.w*v.w;
    #pragma unroll
    for (int o = 16; o > 0; o >>= 1) {
        s  += __shfl_xor_sync(0xffffffffu, s,  o);
        ss += __shfl_xor_sync(0xffffffffu, ss, o);
    }
    __shared__ float sh[16];
    int w = threadIdx.x >> 5, ln = threadIdx.x & 31;
    if (ln == 0) { sh[w] = s; sh[w + 8] = ss; }
    __syncthreads();
    float fs = 0.f, fss = 0.f;
    #pragma unroll
    for (int k = 0; k < 8; k++) { fs += sh[k]; fss += sh[k + 8]; }
    float mu   = fs  * (1.f / DM);
    float var  = fss * (1.f / DM) - mu * mu;
    float rstd = rsqrtf(var + 1e-5f);

    const __half* gp = gb + (size_t)row * gbStride + gbOff;
    __half2 ga01 = *(const __half2*)(gp + i);
    __half2 ga23 = *(const __half2*)(gp + i + 2);
    __half2 be01 = *(const __half2*)(gp + DM + i);
    __half2 be23 = *(const __half2*)(gp + DM + i + 2);
    float2 ga0 = __half22float2(ga01), ga1 = __half22float2(ga23);
    float2 be0 = __half22float2(be01), be1 = __half22float2(be23);
    float o0 = (v.x - mu) * rstd * (1.f + ga0.x) + be0.x;
    float o1 = (v.y - mu) * rstd * (1.f + ga0.y) + be0.y;
    float o2 = (v.z - mu) * rstd * (1.f + ga1.x) + be1.x;
    float o3 = (v.w - mu) * rstd * (1.f + ga1.y) + be1.y;
    __half2* op = (__half2*)(out + (size_t)row * DM + i);
    op[0] = __floats2half2_rn(o0, o1);
    op[1] = __floats2half2_rn(o2, o3);
}

// ---------------------------------------------------------------------------
// Launch
// ---------------------------------------------------------------------------
extern "C" void kernel_launch(void* const* d_in, const int* in_sizes, int n_in,
                              void* d_out, int out_size)
{
    const float* x          = (const float*)d_in[0];
    const float* cond       = (const float*)d_in[1];
    const float* p1_w       = (const float*)d_in[2];
    const float* p1_b       = (const float*)d_in[3];
    const float* qkv_w      = (const float*)d_in[4];
    const float* attn_out_w = (const float*)d_in[5];
    const float* p2_w       = (const float*)d_in[6];
    const float* p2_b       = (const float*)d_in[7];
    const float* ffn_w1     = (const float*)d_in[8];
    const float* ffn_b1     = (const float*)d_in[9];
    const float* ffn_w2     = (const float*)d_in[10];
    const float* ffn_b2     = (const float*)d_in[11];
    float* out = (float*)d_out;

    __half *sc, *h, *attn, *ff, *qkv, *gb;
    float *x2, *b_p12;
    __half *wt_p12, *wt_qkv, *wt_ao, *wt_f1, *wt_f2;
    cudaGetSymbolAddress((void**)&sc,     g_sc);
    cudaGetSymbolAddress((void**)&gb,     g_gb);
    cudaGetSymbolAddress((void**)&h,      g_h);
    cudaGetSymbolAddress((void**)&qkv,    g_qkv);
    cudaGetSymbolAddress((void**)&attn,   g_attn);
    cudaGetSymbolAddress((void**)&x2,     g_x2);
    cudaGetSymbolAddress((void**)&ff,     g_ff);
    cudaGetSymbolAddress((void**)&wt_p12, g_wt_p12);
    cudaGetSymbolAddress((void**)&wt_qkv, g_wt_qkv);
    cudaGetSymbolAddress((void**)&wt_ao,  g_wt_ao);
    cudaGetSymbolAddress((void**)&wt_f1,  g_wt_f1);
    cudaGetSymbolAddress((void**)&wt_f2,  g_wt_f2);
    cudaGetSymbolAddress((void**)&b_p12,  g_b_p12);

    cudaFuncSetAttribute(hgemm<1,0,0,1>, cudaFuncAttributeMaxDynamicSharedMemorySize, TG_SMEM);
    cudaFuncSetAttribute(hgemm<0,0,0,1>, cudaFuncAttributeMaxDynamicSharedMemorySize, TG_SMEM);
    cudaFuncSetAttribute(hgemm<0,0,1,0>, cudaFuncAttributeMaxDynamicSharedMemorySize, TG_SMEM);
    cudaFuncSetAttribute(hgemm<1,1,0,1>, cudaFuncAttributeMaxDynamicSharedMemorySize, TG_SMEM);
    cudaFuncSetAttribute(hgemm<1,0,1,0>, cudaFuncAttributeMaxDynamicSharedMemorySize, TG_SMEM);
    cudaFuncSetAttribute(fattn, cudaFuncAttributeMaxDynamicSharedMemorySize, ATT_SMEM);

    // Weight transposes (64x64 tiles)
    transpose_h<<<dim3(2048/64,  512/64), 256>>>(p1_w, wt_p12,              512, 2048);
    transpose_h<<<dim3(2048/64,  512/64), 256>>>(p2_w, wt_p12 + 2048 * 512, 512, 2048);
    transpose_h<<<dim3(3072/64, 1024/64), 256>>>(qkv_w,      wt_qkv, 1024, 3072);
    transpose_h<<<dim3(1024/64, 1024/64), 256>>>(attn_out_w, wt_ao,  1024, 1024);
    transpose_h<<<dim3(4096/64, 1024/64), 256>>>(ffn_w1,     wt_f1,  1024, 4096);
    transpose_h<<<dim3(1024/64, 4096/64), 256>>>(ffn_w2,     wt_f2,  4096, 1024);
    concat_bias<<<(4 * DM + 255) / 256, 256>>>(p1_b, p2_b, b_p12);

    // 1. sc = silu(cond) -> fp16
    silu_kernel<<<(BS_TOK * DC / 4 + 255) / 256, 256>>>(cond, sc, BS_TOK * DC / 4);
    // 2. gb = sc @ [p1|p2] + bias -> fp16   (M=4096, N=4096, K=512)
    hgemm<1,0,0,1><<<dim3(4096/128, BS_TOK/128), 256, TG_SMEM>>>(
        sc, wt_p12, b_p12, nullptr, gb, BS_TOK, 4096, DC);
    // 3. h = adaln(x, gb[:, 0:2048]) -> fp16
    adaln_kernel<<<BS_TOK, 256>>>(x, gb, 4096, 0, h);
    // 4. qkv = h @ qkv_w -> fp16
    hgemm<0,0,0,1><<<dim3(3072/128, BS_TOK/128), 256, TG_SMEM>>>(
        h, wt_qkv, nullptr, nullptr, qkv, BS_TOK, 3072, DM);
    // 5. attention -> fp16
    fattn<<<dim3(SEQ/128, NH, 2), 256, ATT_SMEM>>>(qkv, attn);
    // 6. x2 = x + attn @ attn_out_w (fp32 out)
    hgemm<0,0,1,0><<<dim3(1024/128, BS_TOK/128), 256, TG_SMEM>>>(
        attn, wt_ao, nullptr, x, x2, BS_TOK, 1024, DM);
    // 7. h = adaln(x2, gb[:, 2048:4096]) -> fp16
    adaln_kernel<<<BS_TOK, 256>>>(x2, gb, 4096, 2048, h);
    // 8. ff = gelu(h @ ffn_w1 + ffn_b1) -> fp16
    hgemm<1,1,0,1><<<dim3(DFF/128, BS_TOK/128), 256, TG_SMEM>>>(
        h, wt_f1, ffn_b1, nullptr, ff, BS_TOK, DFF, DM);
    // 9. out = x2 + ff @ ffn_w2 + ffn_b2 (fp32 out)
    hgemm<1,0,1,0><<<dim3(1024/128, BS_TOK/128), 256, TG_SMEM>>>(
        ff, wt_f2, ffn_b2, x2, out, BS_TOK, 1024, DFF);
}

// round 17
// speedup vs baseline: 1.1162x; 1.0257x over previous
#include <cuda_runtime.h>
#include <cuda_fp16.h>
#include <math.h>
#include <stdint.h>

// ---------------------------------------------------------------------------
// DecoderBlock: B=2, S=2048, D_MODEL=1024, D_COND=512, H=16, d=64, FF=4096
// Round 17: single merged transpose launch (table-driven); hgemm cp.async
// issue spread across kk-loop. Otherwise identical to round 13/16.
// ---------------------------------------------------------------------------

#define BS_TOK   4096
#define DM       1024
#define DC       512
#define DFF      4096
#define NH       16
#define DH       64
#define SEQ      2048

// ---------------- scratch ---------------------------------------------------
__device__ __half g_sc  [BS_TOK * DC];
__device__ __half g_gb  [BS_TOK * 4 * DM];
__device__ __half g_h   [BS_TOK * DM];
__device__ __half g_qkv [BS_TOK * 3 * DM];
__device__ __half g_attn[BS_TOK * DM];
__device__ float  g_x2  [BS_TOK * DM];
__device__ __half g_ff  [BS_TOK * DFF];
__device__ __half g_wt_p12[4 * DM * DC];
__device__ __half g_wt_qkv[3 * DM * DM];
__device__ __half g_wt_ao [DM * DM];
__device__ __half g_wt_f1 [DFF * DM];
__device__ __half g_wt_f2 [DM * DFF];
__device__ float  g_b_p12 [4 * DM];

// ---------------- helpers ---------------------------------------------------
__device__ __forceinline__ uint32_t smem_u32(const void* p) {
    uint32_t a;
    asm("{ .reg .u64 t; cvta.to.shared.u64 t, %1; cvt.u32.u64 %0, t; }"
        : "=r"(a) : "l"(p));
    return a;
}
__device__ __forceinline__ void cp_async16(uint32_t dst, const void* src) {
    asm volatile("cp.async.cg.shared.global [%0], [%1], 16;"
                 :: "r"(dst), "l"(src) : "memory");
}
#define CP_COMMIT() asm volatile("cp.async.commit_group;" ::: "memory")
#define CP_WAIT(n)  asm volatile("cp.async.wait_group %0;" :: "n"(n) : "memory")

__device__ __forceinline__ void mma_f16(float* c, const uint32_t* a, const uint32_t* b) {
    asm volatile("mma.sync.aligned.m16n8k16.row.col.f32.f16.f16.f32 "
        "{%0,%1,%2,%3}, {%4,%5,%6,%7}, {%8,%9}, {%0,%1,%2,%3};"
        : "+f"(c[0]), "+f"(c[1]), "+f"(c[2]), "+f"(c[3])
        : "r"(a[0]), "r"(a[1]), "r"(a[2]), "r"(a[3]), "r"(b[0]), "r"(b[1]));
}
#define LDMX4(r0, r1, r2, r3, addr)                                           \
    asm volatile("ldmatrix.sync.aligned.m8n8.x4.shared.b16 {%0,%1,%2,%3}, [%4];" \
        : "=r"(r0), "=r"(r1), "=r"(r2), "=r"(r3) : "r"(addr))
#define LDMX4T(r0, r1, r2, r3, addr)                                          \
    asm volatile("ldmatrix.sync.aligned.m8n8.x4.trans.shared.b16 {%0,%1,%2,%3}, [%4];" \
        : "=r"(r0), "=r"(r1), "=r"(r2), "=r"(r3) : "r"(addr))

__device__ __forceinline__ uint32_t packh2(float x, float y) {
    __half2 h = __floats2half2_rn(x, y);
    return *(uint32_t*)&h;
}

#define HXS(r, c) ((uint32_t)((r) * 128 + (((c) ^ ((r) & 7)) << 4)))

// ---------------------------------------------------------------------------
// fp16 mma GEMM: C[M,N] = A[M,K] @ Bt[N,K]^T (+bias)(+gelu)(+res)
// BM=BN=128, BK=64, 3-stage cp.async (issue spread over kk), 2 CTAs/SM.
// ---------------------------------------------------------------------------
#define TG_SMEM 98304

template<int BIAS, int GELU, int RES, int OUTH>
__global__ __launch_bounds__(256, 2) void hgemm(
    const __half* __restrict__ A, const __half* __restrict__ Bt,
    const float* __restrict__ bias, const float* __restrict__ res,
    void* __restrict__ Cv, int M, int N, int K)
{
    extern __shared__ __align__(1024) char smem_raw[];
    const uint32_t sA = smem_u32(smem_raw);
    const uint32_t sB = sA + 3 * 16384;

    const int tid  = threadIdx.x;
    const int wid  = tid >> 5;
    const int lane = tid & 31;
    const int bx = blockIdx.x, by = blockIdx.y;

    const __half* Ab = A  + (size_t)(by * 128) * K;
    const __half* Bb = Bt + (size_t)(bx * 128) * K;
    const int S = K >> 6;

    const int lr = tid >> 3;
    const int lc = tid & 7;

    auto issue_full = [&](int s, int st) {
        const int k0 = s * 64;
        const uint32_t ao = sA + st * 16384;
        const uint32_t bo = sB + st * 16384;
        #pragma unroll
        for (int t = 0; t < 4; t++) {
            int r = lr + t * 32;
            uint32_t off = HXS(r, lc);
            cp_async16(ao + off, Ab + (size_t)r * K + k0 + lc * 8);
            cp_async16(bo + off, Bb + (size_t)r * K + k0 + lc * 8);
        }
        CP_COMMIT();
    };

    float acc[4][4][4];
    #pragma unroll
    for (int i = 0; i < 4; i++)
        #pragma unroll
        for (int j = 0; j < 4; j++)
            #pragma unroll
            for (int k = 0; k < 4; k++) acc[i][j][k] = 0.f;

    const int wm = (wid >> 2) * 64;
    const int wn = (wid & 3) * 32;
    const int g  = lane >> 2;
    const int tg = lane & 3;
    const int rr  = lane & 7;
    const int sub = lane >> 3;

    uint32_t aRowOff[4], aMask[4];
    const int khalfA = sub >> 1;
    #pragma unroll
    for (int mt = 0; mt < 4; mt++) {
        int row = wm + mt * 16 + (sub & 1) * 8 + rr;
        aRowOff[mt] = (uint32_t)(row * 128);
        aMask[mt]   = (uint32_t)(row & 7);
    }
    uint32_t bRowOff[2], bMask[2];
    const int khalfB = sub & 1;
    #pragma unroll
    for (int ntp = 0; ntp < 2; ntp++) {
        int row = wn + (ntp * 2 + (sub >> 1)) * 8 + rr;
        bRowOff[ntp] = (uint32_t)(row * 128);
        bMask[ntp]   = (uint32_t)(row & 7);
    }

    issue_full(0, 0);
    issue_full(1, 1);

    for (int s = 0; s < S; s++) {
        if (s + 1 < S) { CP_WAIT(1); } else { CP_WAIT(0); }
        __syncthreads();   // compute(s-1) done everywhere; buffer (s+2)%3 safe

        const bool pf = (s + 2 < S);
        const int s2 = s + 2;
        const uint32_t ao2 = sA + (s2 % 3) * 16384;
        const uint32_t bo2 = sB + (s2 % 3) * 16384;
        const int k02 = s2 * 64;

        const uint32_t aBase = sA + (s % 3) * 16384;
        const uint32_t bBase = sB + (s % 3) * 16384;
        #pragma unroll
        for (int kk = 0; kk < 4; kk++) {
            // spread next-stage loads: 2 cp.async per kk-step
            if (pf) {
                int r = lr + kk * 32;
                uint32_t off = HXS(r, lc);
                cp_async16(ao2 + off, Ab + (size_t)r * K + k02 + lc * 8);
                cp_async16(bo2 + off, Bb + (size_t)r * K + k02 + lc * 8);
            }
            uint32_t a[4][4], b[4][2];
            #pragma unroll
            for (int mt = 0; mt < 4; mt++) {
                uint32_t addr = aBase + aRowOff[mt]
                              + (((uint32_t)(kk * 2 + khalfA) ^ aMask[mt]) << 4);
                LDMX4(a[mt][0], a[mt][1], a[mt][2], a[mt][3], addr);
            }
            #pragma unroll
            for (int ntp = 0; ntp < 2; ntp++) {
                uint32_t addr = bBase + bRowOff[ntp]
                              + (((uint32_t)(kk * 2 + khalfB) ^ bMask[ntp]) << 4);
                LDMX4(b[ntp * 2][0], b[ntp * 2][1], b[ntp * 2 + 1][0], b[ntp * 2 + 1][1], addr);
            }
            #pragma unroll
            for (int mt = 0; mt < 4; mt++)
                #pragma unroll
                for (int nt = 0; nt < 4; nt++)
                    mma_f16(acc[mt][nt], a[mt], b[nt]);
        }
        if (pf) CP_COMMIT();
    }

    #pragma unroll
    for (int mt = 0; mt < 4; mt++) {
        #pragma unroll
        for (int hh = 0; hh < 2; hh++) {
            const int row = by * 128 + wm + mt * 16 + g + hh * 8;
            const float* Rr = RES ? (res + (size_t)row * N) : (const float*)0;
            #pragma unroll
            for (int nt = 0; nt < 4; nt++) {
                const int col = bx * 128 + wn + nt * 8 + tg * 2;
                float v0 = acc[mt][nt][hh * 2 + 0];
                float v1 = acc[mt][nt][hh * 2 + 1];
                if (BIAS) { v0 += bias[col]; v1 += bias[col + 1]; }
                if (GELU) {
                    v0 = 0.5f * v0 * (1.f + erff(v0 * 0.70710678118654752f));
                    v1 = 0.5f * v1 * (1.f + erff(v1 * 0.70710678118654752f));
                }
                if (RES) { v0 += Rr[col]; v1 += Rr[col + 1]; }
                if (OUTH) {
                    __half2* Ch = (__half2*)((__half*)Cv + (size_t)row * N + col);
                    *Ch = __floats2half2_rn(v0, v1);
                } else {
                    float2* Cf = (float2*)((float*)Cv + (size_t)row * N + col);
                    *Cf = make_float2(v0, v1);
                }
            }
        }
    }
}

// ---------------------------------------------------------------------------
// fp16 flash attention (unchanged)
// ---------------------------------------------------------------------------
#define ATT_SMEM 40960
#define NKV      (SEQ / 32)

__global__ __launch_bounds__(256) void fattn(
    const __half* __restrict__ qkv, __half* __restrict__ out)
{
    extern __shared__ __align__(1024) char sm[];
    const uint32_t sb = smem_u32(sm);
    const uint32_t QOFF = 0, KOFF = 16384, VOFF = 28672;

    const int tid = threadIdx.x, wid = tid >> 5, lane = tid & 31;
    const int g = lane >> 2, tg = lane & 3;
    const int rr = lane & 7, sub = lane >> 3;
    const int wm = wid * 16;
    const int qb = blockIdx.x, h = blockIdx.y, b = blockIdx.z;
    const size_t tok0 = (size_t)b * SEQ + (size_t)qb * 128;
    const __half* qbase = qkv + tok0 * (3 * DM) + h * DH;

    #pragma unroll
    for (int t = 0; t < 4; t++) {
        int idx = tid + t * 256;
        int r = idx >> 3, c = idx & 7;
        cp_async16(sb + QOFF + HXS(r, c), qbase + (size_t)r * (3 * DM) + c * 8);
    }
    auto issue_kv = [&](int it) {
        const int buf = it % 3;
        const uint32_t base = sb + (tid < 128 ? KOFF : VOFF) + buf * 4096;
        const int seg = (tid < 128 ? DM : 2 * DM);
        #pragma unroll
        for (int t = 0; t < 2; t++) {
            const int chunk = (tid & 127) + t * 128;
            const int r = chunk >> 3, c = chunk & 7;
            cp_async16(base + HXS(r, c),
                       qkv + ((size_t)b * SEQ + it * 32 + r) * (3 * DM) + seg + h * DH + c * 8);
        }
        CP_COMMIT();
    };
    issue_kv(0);
    issue_kv(1);
    issue_kv(2);

    CP_WAIT(2);
    __syncthreads();

    uint32_t qf[4][4];
    {
        const int row = wm + (sub & 1) * 8 + rr;
        const uint32_t rowOff = (uint32_t)(row * 128);
        const uint32_t mask = (uint32_t)(row & 7);
        const int khalf = sub >> 1;
        #pragma unroll
        for (int kk = 0; kk < 4; kk++) {
            uint32_t addr = sb + QOFF + rowOff + (((uint32_t)(kk * 2 + khalf) ^ mask) << 4);
            LDMX4(qf[kk][0], qf[kk][1], qf[kk][2], qf[kk][3], addr);
        }
    }

    float oa[8][4];
    #pragma unroll
    for (int i = 0; i < 8; i++)
        #pragma unroll
        for (int j = 0; j < 4; j++) oa[i][j] = 0.f;
    float m0 = -1e30f, m1 = -1e30f, l0 = 0.f, l1 = 0.f;

    const int kRow = (sub >> 1) * 8 + rr;
    const int kHalf = sub & 1;

    for (int it = 0; it < NKV; it++) {
        if (it < NKV - 2)      { CP_WAIT(2); }
        else if (it == NKV - 2){ CP_WAIT(1); }
        else                   { CP_WAIT(0); }
        __syncthreads();

        const int buf = it % 3;
        const uint32_t kbuf = sb + KOFF + buf * 4096;
        const uint32_t vbuf = sb + VOFF + buf * 4096;

        float sf[4][4];
        #pragma unroll
        for (int nt = 0; nt < 4; nt++)
            #pragma unroll
            for (int e = 0; e < 4; e++) sf[nt][e] = 0.f;

        #pragma unroll
        for (int kk = 0; kk < 4; kk++) {
            uint32_t bfr[4][2];
            #pragma unroll
            for (int ntp = 0; ntp < 2; ntp++) {
                const int row = ntp * 16 + kRow;
                uint32_t addr = kbuf + (uint32_t)(row * 128)
                              + (((uint32_t)(kk * 2 + kHalf) ^ (uint32_t)(row & 7)) << 4);
                LDMX4(bfr[ntp * 2][0], bfr[ntp * 2][1],
                      bfr[ntp * 2 + 1][0], bfr[ntp * 2 + 1][1], addr);
            }
            #pragma unroll
            for (int nt = 0; nt < 4; nt++)
                mma_f16(sf[nt], qf[kk], bfr[nt]);
        }

        float mx0 = -1e30f, mx1 = -1e30f;
        #pragma unroll
        for (int nt = 0; nt < 4; nt++) {
            #pragma unroll
            for (int e = 0; e < 4; e++) sf[nt][e] *= 0.125f;
            mx0 = fmaxf(mx0, fmaxf(sf[nt][0], sf[nt][1]));
            mx1 = fmaxf(mx1, fmaxf(sf[nt][2], sf[nt][3]));
        }
        mx0 = fmaxf(mx0, __shfl_xor_sync(0xffffffffu, mx0, 1));
        mx0 = fmaxf(mx0, __shfl_xor_sync(0xffffffffu, mx0, 2));
        mx1 = fmaxf(mx1, __shfl_xor_sync(0xffffffffu, mx1, 1));
        mx1 = fmaxf(mx1, __shfl_xor_sync(0xffffffffu, mx1, 2));
        const float nm0 = fmaxf(m0, mx0), nm1 = fmaxf(m1, mx1);
        const float cr0 = __expf(m0 - nm0), cr1 = __expf(m1 - nm1);
        m0 = nm0; m1 = nm1;

        float ls0 = 0.f, ls1 = 0.f;
        #pragma unroll
        for (int nt = 0; nt < 4; nt++) {
            sf[nt][0] = __expf(sf[nt][0] - m0);
            sf[nt][1] = __expf(sf[nt][1] - m0);
            sf[nt][2] = __expf(sf[nt][2] - m1);
            sf[nt][3] = __expf(sf[nt][3] - m1);
            ls0 += sf[nt][0] + sf[nt][1];
            ls1 += sf[nt][2] + sf[nt][3];
        }
        ls0 += __shfl_xor_sync(0xffffffffu, ls0, 1);
        ls0 += __shfl_xor_sync(0xffffffffu, ls0, 2);
        ls1 += __shfl_xor_sync(0xffffffffu, ls1, 1);
        ls1 += __shfl_xor_sync(0xffffffffu, ls1, 2);
        l0 = l0 * cr0 + ls0;
        l1 = l1 * cr1 + ls1;

        #pragma unroll
        for (int nt = 0; nt < 8; nt++) {
            oa[nt][0] *= cr0; oa[nt][1] *= cr0;
            oa[nt][2] *= cr1; oa[nt][3] *= cr1;
        }

        #pragma unroll
        for (int kk = 0; kk < 2; kk++) {
            uint32_t a[4];
            a[0] = packh2(sf[kk * 2][0],     sf[kk * 2][1]);
            a[1] = packh2(sf[kk * 2][2],     sf[kk * 2][3]);
            a[2] = packh2(sf[kk * 2 + 1][0], sf[kk * 2 + 1][1]);
            a[3] = packh2(sf[kk * 2 + 1][2], sf[kk * 2 + 1][3]);
            const int key = kk * 16 + (sub & 1) * 8 + rr;
            const uint32_t keyOff = (uint32_t)(key * 128);
            const uint32_t keyMask = (uint32_t)(key & 7);
            #pragma unroll
            for (int ntp = 0; ntp < 4; ntp++) {
                uint32_t b0[2], b1[2];
                uint32_t addr = vbuf + keyOff
                              + (((uint32_t)(ntp * 2 + (sub >> 1)) ^ keyMask) << 4);
                LDMX4T(b0[0], b0[1], b1[0], b1[1], addr);
                mma_f16(oa[ntp * 2],     a, b0);
                mma_f16(oa[ntp * 2 + 1], a, b1);
            }
        }
        __syncthreads();
        if (it + 3 < NKV) issue_kv(it + 3);
    }

    const float inv0 = 1.f / l0, inv1 = 1.f / l1;
    #pragma unroll
    for (int nt = 0; nt < 8; nt++) {
        const int col = h * DH + nt * 8 + 2 * tg;
        __half* o0 = out + (tok0 + wm + g) * DM + col;
        __half* o1 = out + (tok0 + wm + g + 8) * DM + col;
        *(__half2*)o0 = __floats2half2_rn(oa[nt][0] * inv0, oa[nt][1] * inv0);
        *(__half2*)o1 = __floats2half2_rn(oa[nt][2] * inv1, oa[nt][3] * inv1);
    }
}

// ---------------------------------------------------------------------------
// Merged weight transpose: one launch, table of 6 jobs, 64x64 tiles.
// ---------------------------------------------------------------------------
struct TJobs {
    const float* src[6];
    __half*      dst[6];
    int K[6], N[6];
    int start[7];   // tile prefix sums
};

__global__ __launch_bounds__(256) void transpose_all(TJobs jobs) {
    const int bid = blockIdx.x;
    int j = 0;
    #pragma unroll
    for (int i = 1; i < 6; i++) if (bid >= jobs.start[i]) j = i;
    const float* W  = jobs.src[j];
    __half*      Wt = jobs.dst[j];
    const int K = jobs.K[j], N = jobs.N[j];
    const int lt  = bid - jobs.start[j];
    const int tpr = N >> 6;
    const int n0 = (lt % tpr) * 64, k0 = (lt / tpr) * 64;

    __shared__ float t[64][65];
    const int tc = threadIdx.x & 15;
    const int tr = threadIdx.x >> 4;
    #pragma unroll
    for (int i = 0; i < 4; i++) {
        int k = tr + i * 16;
        float4 v = *(const float4*)(W + (size_t)(k0 + k) * N + n0 + tc * 4);
        t[k][tc * 4 + 0] = v.x; t[k][tc * 4 + 1] = v.y;
        t[k][tc * 4 + 2] = v.z; t[k][tc * 4 + 3] = v.w;
    }
    __syncthreads();
    const int k2 = (threadIdx.x & 31) * 2;
    const int nr = threadIdx.x >> 5;
    #pragma unroll
    for (int jj = 0; jj < 8; jj++) {
        int n = nr + jj * 8;
        __half2 h = __floats2half2_rn(t[k2][n], t[k2 + 1][n]);
        *(__half2*)(Wt + (size_t)(n0 + n) * K + k0 + k2) = h;
    }
}

__global__ void concat_bias(const float* __restrict__ b1, const float* __restrict__ b2,
                            float* __restrict__ o) {
    int i = blockIdx.x * blockDim.x + threadIdx.x;
    if (i < 2 * DM) o[i] = b1[i];
    else            o[i] = b2[i - 2 * DM];
}

// ---------------------------------------------------------------------------
// silu -> fp16
// ---------------------------------------------------------------------------
__global__ void silu_kernel(const float* __restrict__ in, __half* __restrict__ out, int n4) {
    int i = blockIdx.x * blockDim.x + threadIdx.x;
    if (i >= n4) return;
    float4 v = ((const float4*)in)[i];
    __half2 a = __floats2half2_rn(v.x / (1.f + expf(-v.x)), v.y / (1.f + expf(-v.y)));
    __half2 b = __floats2half2_rn(v.z / (1.f + expf(-v.z)), v.w / (1.f + expf(-v.w)));
    __half2* o = (__half2*)(out + (size_t)i * 4);
    o[0] = a; o[1] = b;
}

// ---------------------------------------------------------------------------
// AdaLN (gb fp16) -> fp16
// ---------------------------------------------------------------------------
__global__ __launch_bounds__(256) void adaln_kernel(
    const float* __restrict__ x, const __half* __restrict__ gb, int gbStride,
    int gbOff, __half* __restrict__ out)
{
    int row = blockIdx.x;
    const float* xr = x + (size_t)row * DM;
    int i = threadIdx.x * 4;
    float4 v = *(const float4*)(xr + i);
    float s  = v.x + v.y + v.z + v.w;
    float ss = v.x*v.x + v.y*v.y + v.z*v.z + v.w*v.w;
    #pragma unroll
    for (int o = 16; o > 0; o >>= 1) {
        s  += __shfl_xor_sync(0xffffffffu, s,  o);
        ss += __shfl_xor_sync(0xffffffffu, ss, o);
    }
    __shared__ float sh[16];
    int w = threadIdx.x >> 5, ln = threadIdx.x & 31;
    if (ln == 0) { sh[w] = s; sh[w + 8] = ss; }
    __syncthreads();
    float fs = 0.f, fss = 0.f;
    #pragma unroll
    for (int k = 0; k < 8; k++) { fs += sh[k]; fss += sh[k + 8]; }
    float mu   = fs  * (1.f / DM);
    float var  = fss * (1.f / DM) - mu * mu;
    float rstd = rsqrtf(var + 1e-5f);

    const __half* gp = gb + (size_t)row * gbStride + gbOff;
    __half2 ga01 = *(const __half2*)(gp + i);
    __half2 ga23 = *(const __half2*)(gp + i + 2);
    __half2 be01 = *(const __half2*)(gp + DM + i);
    __half2 be23 = *(const __half2*)(gp + DM + i + 2);
    float2 ga0 = __half22float2(ga01), ga1 = __half22float2(ga23);
    float2 be0 = __half22float2(be01), be1 = __half22float2(be23);
    float o0 = (v.x - mu) * rstd * (1.f + ga0.x) + be0.x;
    float o1 = (v.y - mu) * rstd * (1.f + ga0.y) + be0.y;
    float o2 = (v.z - mu) * rstd * (1.f + ga1.x) + be1.x;
    float o3 = (v.w - mu) * rstd * (1.f + ga1.y) + be1.y;
    __half2* op = (__half2*)(out + (size_t)row * DM + i);
    op[0] = __floats2half2_rn(o0, o1);
    op[1] = __floats2half2_rn(o2, o3);
}

// ---------------------------------------------------------------------------
// Launch
// ---------------------------------------------------------------------------
extern "C" void kernel_launch(void* const* d_in, const int* in_sizes, int n_in,
                              void* d_out, int out_size)
{
    const float* x          = (const float*)d_in[0];
    const float* cond       = (const float*)d_in[1];
    const float* p1_w       = (const float*)d_in[2];
    const float* p1_b       = (const float*)d_in[3];
    const float* qkv_w      = (const float*)d_in[4];
    const float* attn_out_w = (const float*)d_in[5];
    const float* p2_w       = (const float*)d_in[6];
    const float* p2_b       = (const float*)d_in[7];
    const float* ffn_w1     = (const float*)d_in[8];
    const float* ffn_b1     = (const float*)d_in[9];
    const float* ffn_w2     = (const float*)d_in[10];
    const float* ffn_b2     = (const float*)d_in[11];
    float* out = (float*)d_out;

    __half *sc, *h, *attn, *ff, *qkv, *gb;
    float *x2, *b_p12;
    __half *wt_p12, *wt_qkv, *wt_ao, *wt_f1, *wt_f2;
    cudaGetSymbolAddress((void**)&sc,     g_sc);
    cudaGetSymbolAddress((void**)&gb,     g_gb);
    cudaGetSymbolAddress((void**)&h,      g_h);
    cudaGetSymbolAddress((void**)&qkv,    g_qkv);
    cudaGetSymbolAddress((void**)&attn,   g_attn);
    cudaGetSymbolAddress((void**)&x2,     g_x2);
    cudaGetSymbolAddress((void**)&ff,     g_ff);
    cudaGetSymbolAddress((void**)&wt_p12, g_wt_p12);
    cudaGetSymbolAddress((void**)&wt_qkv, g_wt_qkv);
    cudaGetSymbolAddress((void**)&wt_ao,  g_wt_ao);
    cudaGetSymbolAddress((void**)&wt_f1,  g_wt_f1);
    cudaGetSymbolAddress((void**)&wt_f2,  g_wt_f2);
    cudaGetSymbolAddress((void**)&b_p12,  g_b_p12);

    cudaFuncSetAttribute(hgemm<1,0,0,1>, cudaFuncAttributeMaxDynamicSharedMemorySize, TG_SMEM);
    cudaFuncSetAttribute(hgemm<0,0,0,1>, cudaFuncAttributeMaxDynamicSharedMemorySize, TG_SMEM);
    cudaFuncSetAttribute(hgemm<0,0,1,0>, cudaFuncAttributeMaxDynamicSharedMemorySize, TG_SMEM);
    cudaFuncSetAttribute(hgemm<1,1,0,1>, cudaFuncAttributeMaxDynamicSharedMemorySize, TG_SMEM);
    cudaFuncSetAttribute(hgemm<1,0,1,0>, cudaFuncAttributeMaxDynamicSharedMemorySize, TG_SMEM);
    cudaFuncSetAttribute(fattn, cudaFuncAttributeMaxDynamicSharedMemorySize, ATT_SMEM);

    // Single merged transpose launch: 6 jobs, 64x64 tiles.
    TJobs tj;
    tj.src[0] = p1_w;       tj.dst[0] = wt_p12;              tj.K[0] = 512;  tj.N[0] = 2048;
    tj.src[1] = p2_w;       tj.dst[1] = wt_p12 + 2048 * 512; tj.K[1] = 512;  tj.N[1] = 2048;
    tj.src[2] = qkv_w;      tj.dst[2] = wt_qkv;              tj.K[2] = 1024; tj.N[2] = 3072;
    tj.src[3] = attn_out_w; tj.dst[3] = wt_ao;               tj.K[3] = 1024; tj.N[3] = 1024;
    tj.src[4] = ffn_w1;     tj.dst[4] = wt_f1;               tj.K[4] = 1024; tj.N[4] = 4096;
    tj.src[5] = ffn_w2;     tj.dst[5] = wt_f2;               tj.K[5] = 4096; tj.N[5] = 1024;
    int acc_t = 0;
    for (int i = 0; i < 6; i++) {
        tj.start[i] = acc_t;
        acc_t += (tj.N[i] / 64) * (tj.K[i] / 64);
    }
    tj.start[6] = acc_t;
    transpose_all<<<acc_t, 256>>>(tj);
    concat_bias<<<(4 * DM + 255) / 256, 256>>>(p1_b, p2_b, b_p12);

    // 1. sc = silu(cond) -> fp16
    silu_kernel<<<(BS_TOK * DC / 4 + 255) / 256, 256>>>(cond, sc, BS_TOK * DC / 4);
    // 2. gb = sc @ [p1|p2] + bias -> fp16
    hgemm<1,0,0,1><<<dim3(4096/128, BS_TOK/128), 256, TG_SMEM>>>(
        sc, wt_p12, b_p12, nullptr, gb, BS_TOK, 4096, DC);
    // 3. h = adaln(x, gb[:, 0:2048]) -> fp16
    adaln_kernel<<<BS_TOK, 256>>>(x, gb, 4096, 0, h);
    // 4. qkv = h @ qkv_w -> fp16
    hgemm<0,0,0,1><<<dim3(3072/128, BS_TOK/128), 256, TG_SMEM>>>(
        h, wt_qkv, nullptr, nullptr, qkv, BS_TOK, 3072, DM);
    // 5. attention -> fp16
    fattn<<<dim3(SEQ/128, NH, 2), 256, ATT_SMEM>>>(qkv, attn);
    // 6. x2 = x + attn @ attn_out_w (fp32 out)
    hgemm<0,0,1,0><<<dim3(1024/128, BS_TOK/128), 256, TG_SMEM>>>(
        attn, wt_ao, nullptr, x, x2, BS_TOK, 1024, DM);
    // 7. h = adaln(x2, gb[:, 2048:4096]) -> fp16
    adaln_kernel<<<BS_TOK, 256>>>(x2, gb, 4096, 2048, h);
    // 8. ff = gelu(h @ ffn_w1 + ffn_b1) -> fp16
    hgemm<1,1,0,1><<<dim3(DFF/128, BS_TOK/128), 256, TG_SMEM>>>(
        h, wt_f1, ffn_b1, nullptr, ff, BS_TOK, DFF, DM);
    // 9. out = x2 + ff @ ffn_w2 + ffn_b2 (fp32 out)
    hgemm<1,0,1,0><<<dim3(1024/128, BS_TOK/128), 256, TG_SMEM>>>(
        ff, wt_f2, ffn_b2, x2, out, BS_TOK, 1024, DFF);
}